// round 14
// baseline (speedup 1.0000x reference)
#include <cuda_runtime.h>
#include <cuda_bf16.h>
#include <stdint.h>

// ============================================================================
// Problem constants
// ============================================================================
#define N_TOT 8192        // bsz * n_views
#define BSZ   4096
#define DIM   128
#define INV_T 14.285714285714286f   // 1 / 0.07
#define SPAD  136                    // padded SMEM row stride (elements)
#define NTILE 64
#define NPAIR 2080                   // 64*65/2 upper-triangular tiles
#define NCTA_MAIN (NPAIR * 2)        // 2 half-tiles per pair
#define KMOM  12                     // Taylor terms for exp(li*lj)
#define NSLOT 256                    // 32-col-group granularity

typedef unsigned long long u64;

// ============================================================================
// Device globals
// ============================================================================
__device__ __nv_bfloat16 g_F[(size_t)N_TOT * DIM];     // normalized feats bf16
__device__ float g_Ff[(size_t)N_TOT * DIM];            // normalized feats fp32
__device__ float g_pD[(size_t)NSLOT * N_TOT];          // D partials [slot][row]
__device__ float g_Gpart[128 * KMOM * DIM];            // moment partials (2/CTA)
__device__ float g_spart[64 * KMOM];
__device__ float g_G[KMOM * DIM];
__device__ float g_s[KMOM];
__device__ float g_bpart[32];
__device__ unsigned g_cnt;

__constant__ float c_CK[KMOM] = {
    1.0f, 1.0f, 0.5f, 1.6666667e-1f, 4.1666667e-2f, 8.3333333e-3f,
    1.3888889e-3f, 1.9841270e-4f, 2.4801587e-5f, 2.7557319e-6f,
    2.7557319e-7f, 2.5052108e-8f
};

__device__ __forceinline__ uint32_t smem_u32(const void* smem_ptr) {
    uint32_t addr;
    asm("{ .reg .u64 tmp; cvta.to.shared.u64 tmp, %1; cvt.u32.u64 %0, tmp; }"
        : "=r"(addr) : "l"(smem_ptr));
    return addr;
}

// ---- packed f32x2 helpers ----
__device__ __forceinline__ u64 pk2(float a, float b) {
    u64 r;
    asm("mov.b64 %0, {%1,%2};" : "=l"(r)
        : "r"(__float_as_uint(a)), "r"(__float_as_uint(b)));
    return r;
}
__device__ __forceinline__ void upk2(u64 v, float& a, float& b) {
    unsigned x, y;
    asm("mov.b64 {%0,%1}, %2;" : "=r"(x), "=r"(y) : "l"(v));
    a = __uint_as_float(x); b = __uint_as_float(y);
}
__device__ __forceinline__ u64 add2_(u64 a, u64 b) {
    u64 d; asm("add.rn.f32x2 %0,%1,%2;" : "=l"(d) : "l"(a), "l"(b)); return d;
}
__device__ __forceinline__ u64 fma2_(u64 a, u64 b, u64 c) {
    u64 d; asm("fma.rn.f32x2 %0,%1,%2,%3;" : "=l"(d) : "l"(a), "l"(b), "l"(c)); return d;
}
__device__ __forceinline__ float ex2f(float x) {
    float r; asm("ex2.approx.f32 %0,%1;" : "=f"(r) : "f"(x)); return r;
}

// ============================================================================
// Kernel 1 (fused prep): CTA c normalizes rows [c*128, c*128+128) into
//   g_F (bf16), g_Ff (fp32) and SMEM, then computes moment partials.
// ============================================================================
#define MOM_SMEM (128 * DIM * 4 + 128 * KMOM * 4)   // 64KB + 6KB

__global__ void __launch_bounds__(256)
k_prep(const float* __restrict__ feats, const float* __restrict__ labels) {
    extern __shared__ float smem_m[];
    float* sF     = smem_m;                 // [128 * DIM]
    float* s_coef = smem_m + 128 * DIM;     // [128][KMOM]
    int c   = blockIdx.x;
    int tid = threadIdx.x;
    int wid = tid >> 5;
    int lane = tid & 31;

#pragma unroll 4
    for (int i = 0; i < 16; ++i) {
        int j   = wid * 16 + i;
        int row = c * 128 + j;
        int b = row & (BSZ - 1);
        int v = row >> 12;
        float4 x = reinterpret_cast<const float4*>(feats)
                   [(size_t)(b * 2 + v) * (DIM / 4) + lane];
        float ss = fmaf(x.x, x.x, fmaf(x.y, x.y, fmaf(x.z, x.z, x.w * x.w)));
#pragma unroll
        for (int o = 16; o; o >>= 1) ss += __shfl_xor_sync(0xffffffffu, ss, o);
        float inv = rsqrtf(ss + 1e-12f);
        float4 xn;
        xn.x = x.x * inv; xn.y = x.y * inv; xn.z = x.z * inv; xn.w = x.w * inv;
        reinterpret_cast<float4*>(g_Ff)[(size_t)row * (DIM / 4) + lane] = xn;
        reinterpret_cast<float4*>(sF + j * DIM)[lane] = xn;
        __nv_bfloat162 lo = __floats2bfloat162_rn(xn.x, xn.y);
        __nv_bfloat162 hi = __floats2bfloat162_rn(xn.z, xn.w);
        uint2 pk;
        pk.x = *reinterpret_cast<uint32_t*>(&lo);
        pk.y = *reinterpret_cast<uint32_t*>(&hi);
        reinterpret_cast<uint2*>(g_F)[(size_t)row * (DIM / 4) + lane] = pk;
    }
    if (tid < 128) {
        int row = c * 128 + tid;
        float l = __ldg(&labels[row & (BSZ - 1)]);
        float b = expf(-0.5f * l * l);
        float p = b;
#pragma unroll
        for (int k = 0; k < KMOM; ++k) { s_coef[tid * KMOM + k] = p; p *= l; }
    }
    __syncthreads();

    int d = tid & 127;
    int h = tid >> 7;        // row half
    float acc[KMOM];
#pragma unroll
    for (int k = 0; k < KMOM; ++k) acc[k] = 0.f;
#pragma unroll 4
    for (int j = h * 64; j < h * 64 + 64; ++j) {
        float fv = sF[j * DIM + d];
#pragma unroll
        for (int k = 0; k < KMOM; ++k)
            acc[k] = fmaf(s_coef[j * KMOM + k], fv, acc[k]);
    }
#pragma unroll
    for (int k = 0; k < KMOM; ++k)
        g_Gpart[((c * 2 + h) * KMOM + k) * DIM + d] = acc[k];

    if (tid < KMOM) {
        float s = 0.f;
        for (int j = 0; j < 128; ++j) s += s_coef[j * KMOM + tid];
        g_spart[c * KMOM + tid] = s;
    }
}

// ============================================================================
// Kernel 2b: reduce 128 moment partials. Blocks 0..KMOM-1: G_k; block KMOM: s.
// ============================================================================
__global__ void __launch_bounds__(128)
k_moment2() {
    int k = blockIdx.x;
    int tid = threadIdx.x;
    if (k < KMOM) {
        float s = 0.f;
#pragma unroll 8
        for (int p = 0; p < 128; ++p)
            s += g_Gpart[(p * KMOM + k) * DIM + tid];
        g_G[k * DIM + tid] = s;
    } else if (tid < KMOM) {
        float s = 0.f;
        for (int c = 0; c < 64; ++c) s += g_spart[c * KMOM + tid];
        g_s[tid] = s;
    }
}

// ============================================================================
// Kernel 3: 128x64 half-tile Gram kernel. Warp tile 32x32 (32 accs/thread,
//   ~62 regs -> 4 CTAs/SM, 32 warps). No scol SMEM, no post-MMA barrier.
//   Row sums -> slot tJ*4+h*2+cg ; col sums (per 32-row group) -> slot tI*4+rg.
// ============================================================================
#define SMEM_A_OFF 0
#define SMEM_B_OFF (128 * SPAD * 2)                  // 34816
#define SMEM_BYTES (128 * SPAD * 2 + 64 * SPAD * 2)  // 52224

__device__ __forceinline__ void ldmatrix_x4(uint32_t* a, uint32_t addr) {
    asm volatile("ldmatrix.sync.aligned.m8n8.x4.shared.b16 {%0,%1,%2,%3}, [%4];"
                 : "=r"(a[0]), "=r"(a[1]), "=r"(a[2]), "=r"(a[3]) : "r"(addr));
}
__device__ __forceinline__ void mma_bf16(float* c, const uint32_t* a,
                                         uint32_t b0, uint32_t b1) {
    asm volatile(
        "mma.sync.aligned.m16n8k16.row.col.f32.bf16.bf16.f32 "
        "{%0,%1,%2,%3}, {%4,%5,%6,%7}, {%8,%9}, {%0,%1,%2,%3};"
        : "+f"(c[0]), "+f"(c[1]), "+f"(c[2]), "+f"(c[3])
        : "r"(a[0]), "r"(a[1]), "r"(a[2]), "r"(a[3]), "r"(b0), "r"(b1));
}

__global__ void __launch_bounds__(256, 4)
k_main() {
    extern __shared__ char smem[];
    __nv_bfloat16* sA = reinterpret_cast<__nv_bfloat16*>(smem + SMEM_A_OFF);
    __nv_bfloat16* sB = reinterpret_cast<__nv_bfloat16*>(smem + SMEM_B_OFF);

    int tid  = threadIdx.x;
    int wid  = tid >> 5;
    int lane = tid & 31;
    int rg = wid & 3;        // 32-row group
    int cg = wid >> 2;       // 32-col group (0..1 within the 64-col half)

    int bid = blockIdx.x;
    int h = bid & 1;         // which 64-col half of the tile
    int t = bid >> 1;
    int tI;
    {
        float disc = (float)((2 * NTILE + 1) * (2 * NTILE + 1) - 8 * t);
        tI = (int)(((float)(2 * NTILE + 1) - sqrtf(disc)) * 0.5f);
        if (tI < 0) tI = 0;
        if (tI > NTILE - 1) tI = NTILE - 1;
        while (tI + 1 <= NTILE - 1 &&
               (tI + 1) * NTILE - ((tI + 1) * tI) / 2 <= t) ++tI;
        while (tI * NTILE - (tI * (tI - 1)) / 2 > t) --tI;
    }
    int tJ = tI + (t - (tI * NTILE - (tI * (tI - 1)) / 2));
    bool dtile = (tI == tJ);

    // Stage A (128 rows) and B (64 rows at tJ*128 + h*64)
    {
        const uint4* srcA = reinterpret_cast<const uint4*>(g_F + (size_t)tI * 128 * DIM);
        const uint4* srcB = reinterpret_cast<const uint4*>(
            g_F + (size_t)(tJ * 128 + h * 64) * DIM);
#pragma unroll
        for (int it = 0; it < 8; ++it) {
            int c   = it * 256 + tid;
            int row = c >> 4;
            int ci  = c & 15;
            reinterpret_cast<uint4*>(sA + row * SPAD)[ci] = srcA[row * 16 + ci];
        }
#pragma unroll
        for (int it = 0; it < 4; ++it) {
            int c   = it * 256 + tid;
            int row = c >> 4;
            int ci  = c & 15;
            reinterpret_cast<uint4*>(sB + row * SPAD)[ci] = srcB[row * 16 + ci];
        }
    }
    __syncthreads();

    float acc[2][4][4];
#pragma unroll
    for (int mt = 0; mt < 2; ++mt)
#pragma unroll
        for (int nn = 0; nn < 4; ++nn)
#pragma unroll
            for (int e = 0; e < 4; ++e) acc[mt][nn][e] = 0.f;

    uint32_t sA_b = smem_u32(sA);
    uint32_t sB_b = smem_u32(sB);
    uint32_t a_addr0 = sA_b + (uint32_t)(((rg * 32 + (lane & 15)) * SPAD
                                          + ((lane >> 4) << 3)) * 2);
    uint32_t b_addr0 = sB_b
        + (uint32_t)(((cg * 32 + (lane & 7) + ((lane >> 4) << 3)) * SPAD) * 2
                     + (((lane >> 3) & 1) << 4));

#pragma unroll
    for (int kc = 0; kc < 8; ++kc) {
        uint32_t a0[4], a1[4], b0[4], b1[4];
        ldmatrix_x4(a0, a_addr0 + (uint32_t)(kc * 32));
        ldmatrix_x4(a1, a_addr0 + (uint32_t)(16 * SPAD * 2 + kc * 32));
        ldmatrix_x4(b0, b_addr0 + (uint32_t)(kc * 32));
        ldmatrix_x4(b1, b_addr0 + (uint32_t)(16 * SPAD * 2 + kc * 32));
        mma_bf16(acc[0][0], a0, b0[0], b0[1]);
        mma_bf16(acc[1][0], a1, b0[0], b0[1]);
        mma_bf16(acc[0][1], a0, b0[2], b0[3]);
        mma_bf16(acc[1][1], a1, b0[2], b0[3]);
        mma_bf16(acc[0][2], a0, b1[0], b1[1]);
        mma_bf16(acc[1][2], a1, b1[0], b1[1]);
        mma_bf16(acc[0][3], a0, b1[2], b1[3]);
        mma_bf16(acc[1][3], a1, b1[2], b1[3]);
    }
    // no barrier: epilogue is register/shfl/global only

    const float C2s = 20.609929f;                  // INV_T * log2(e)
    const u64 C2p = pk2(C2s, C2s);
    const u64 C3p = pk2(-C2s, -C2s);

    int rl = rg * 32 + (lane >> 2);
    int gcbase = tJ * 128 + h * 64 + cg * 32;

    if (!dtile) {
        u64 sD2[4] = {0, 0, 0, 0};
#pragma unroll
        for (int nn = 0; nn < 4; ++nn) {
            u64 cD2 = 0;
#pragma unroll
            for (int mt = 0; mt < 2; ++mt) {
#pragma unroll
                for (int ee = 0; ee < 2; ++ee) {
                    int q = mt * 2 + ee;
                    u64 cos2 = pk2(acc[mt][nn][ee * 2], acc[mt][nn][ee * 2 + 1]);
                    u64 ea = fma2_(cos2, C2p, C3p);
                    float e0, e1; upk2(ea, e0, e1);
                    u64 ev = pk2(ex2f(e0), ex2f(e1));
                    sD2[q] = add2_(sD2[q], ev);
                    cD2 = add2_(cD2, ev);
                }
            }
            // column sums over this warp's 32 rows -> slot tI*4+rg
            float d0, d1; upk2(cD2, d0, d1);
#pragma unroll
            for (int o = 4; o <= 16; o <<= 1) {
                d0 += __shfl_xor_sync(0xffffffffu, d0, o);
                d1 += __shfl_xor_sync(0xffffffffu, d1, o);
            }
            if ((lane >> 2) == 0) {
                int gc = gcbase + nn * 8 + ((lane & 3) << 1);
                int slot = tI * 4 + rg;
                float2 fd = {d0, d1};
                *reinterpret_cast<float2*>(&g_pD[(size_t)slot * N_TOT + gc]) = fd;
            }
        }
        // row sums over this warp's 32 cols -> slot tJ*4+h*2+cg
#pragma unroll
        for (int q = 0; q < 4; ++q) {
            float d0, d1;
            upk2(sD2[q], d0, d1);
            float rD = d0 + d1;
            rD += __shfl_xor_sync(0xffffffffu, rD, 1);
            rD += __shfl_xor_sync(0xffffffffu, rD, 2);
            if ((lane & 3) == 0) {
                int slot = tJ * 4 + h * 2 + cg;
                int gi = tI * 128 + rl + q * 8;
                g_pD[(size_t)slot * N_TOT + gi] = rD;
            }
        }
    } else {
        // diagonal tiles: rows only, skip j==i
        float sDr[4] = {0.f, 0.f, 0.f, 0.f};
#pragma unroll
        for (int nn = 0; nn < 4; ++nn) {
            int clbase = h * 64 + cg * 32 + nn * 8 + ((lane & 3) << 1);
#pragma unroll
            for (int mt = 0; mt < 2; ++mt) {
#pragma unroll
                for (int e = 0; e < 4; ++e) {
                    int q  = mt * 2 + (e >> 1);
                    int rr = rl + q * 8;
                    int cc = clbase + (e & 1);
                    float ev = (rr == cc) ? 0.f
                             : ex2f(fmaf(acc[mt][nn][e], C2s, -C2s));
                    sDr[q] += ev;
                }
            }
        }
#pragma unroll
        for (int q = 0; q < 4; ++q) {
            sDr[q] += __shfl_xor_sync(0xffffffffu, sDr[q], 1);
            sDr[q] += __shfl_xor_sync(0xffffffffu, sDr[q], 2);
            if ((lane & 3) == 0) {
                int slot = tJ * 4 + h * 2 + cg;
                int gi = tI * 128 + rl + q * 8;
                g_pD[(size_t)slot * N_TOT + gi] = sDr[q];
            }
        }
    }
}

// ============================================================================
// Kernel 4: fused final — thread = row; 256 coalesced D slots; moments with
//   12-way ILP; loss + fused global mean.
// ============================================================================
__global__ void __launch_bounds__(256)
k_final(const float* __restrict__ labels, float* __restrict__ out) {
    __shared__ float sG[KMOM * DIM];
    __shared__ float sS[KMOM];
    __shared__ float red[8];
    __shared__ bool s_last;
    int tid = threadIdx.x;
    int row = blockIdx.x * 256 + tid;    // 32 CTAs x 256 = 8192
    for (int i = tid; i < KMOM * DIM; i += 256) sG[i] = g_G[i];
    if (tid < KMOM) sS[tid] = g_s[tid];
    __syncthreads();

    float l = __ldg(&labels[row & (BSZ - 1)]);

    float D = 0.f;
#pragma unroll 8
    for (int s = 0; s < NSLOT; ++s)
        D += g_pD[(size_t)s * N_TOT + row];

    float dkp[KMOM];
#pragma unroll
    for (int k = 0; k < KMOM; ++k) dkp[k] = 0.f;
    const float4* fp = reinterpret_cast<const float4*>(g_Ff + (size_t)row * DIM);
#pragma unroll
    for (int ch = 0; ch < 8; ++ch) {
        float4 f0 = __ldg(&fp[ch * 4 + 0]);
        float4 f1 = __ldg(&fp[ch * 4 + 1]);
        float4 f2 = __ldg(&fp[ch * 4 + 2]);
        float4 f3 = __ldg(&fp[ch * 4 + 3]);
#pragma unroll
        for (int k = 0; k < KMOM; ++k) {
            const float* gk = sG + k * DIM + ch * 16;
            float d = dkp[k];
            d = fmaf(f0.x, gk[0],  d); d = fmaf(f0.y, gk[1],  d);
            d = fmaf(f0.z, gk[2],  d); d = fmaf(f0.w, gk[3],  d);
            d = fmaf(f1.x, gk[4],  d); d = fmaf(f1.y, gk[5],  d);
            d = fmaf(f1.z, gk[6],  d); d = fmaf(f1.w, gk[7],  d);
            d = fmaf(f2.x, gk[8],  d); d = fmaf(f2.y, gk[9],  d);
            d = fmaf(f2.z, gk[10], d); d = fmaf(f2.w, gk[11], d);
            d = fmaf(f3.x, gk[12], d); d = fmaf(f3.y, gk[13], d);
            d = fmaf(f3.z, gk[14], d); d = fmaf(f3.w, gk[15], d);
            dkp[k] = d;
        }
    }

    float val = 0.f, Wv = 0.f, p = 1.f;
#pragma unroll
    for (int k = 0; k < KMOM; ++k) {
        float tk = c_CK[k] * p;
        p *= l;
        val = fmaf(tk, dkp[k], val);
        Wv  = fmaf(tk, sS[k], Wv);
    }

    float loss = -((val / Wv - 1.0f) * INV_T - logf(D + 1e-8f));

#pragma unroll
    for (int o = 16; o; o >>= 1) loss += __shfl_xor_sync(0xffffffffu, loss, o);
    if ((tid & 31) == 0) red[tid >> 5] = loss;
    __syncthreads();
    if (tid < 8) {
        float v = red[tid];
#pragma unroll
        for (int o = 4; o; o >>= 1) v += __shfl_xor_sync(0xffu, v, o);
        if (tid == 0) g_bpart[blockIdx.x] = v;
    }
    __threadfence();
    if (tid == 0) s_last = (atomicAdd(&g_cnt, 1u) == 31u);
    __syncthreads();
    if (s_last && tid < 32) {
        float v;
        asm volatile("ld.global.cg.f32 %0, [%1];" : "=f"(v) : "l"(&g_bpart[tid]));
#pragma unroll
        for (int o = 16; o; o >>= 1) v += __shfl_xor_sync(0xffffffffu, v, o);
        if (tid == 0) {
            out[0] = v * (1.0f / (float)N_TOT);
            g_cnt = 0u;   // reset for next graph replay
        }
    }
}

// ============================================================================
// Launch
// ============================================================================
extern "C" void kernel_launch(void* const* d_in, const int* in_sizes, int n_in,
                              void* d_out, int out_size) {
    const float* feats  = (const float*)d_in[0];
    const float* labels = (const float*)d_in[1];
    if (n_in >= 2 && in_sizes[0] == BSZ && in_sizes[1] != BSZ) {
        feats  = (const float*)d_in[1];
        labels = (const float*)d_in[0];
    }

    cudaFuncSetAttribute(k_main, cudaFuncAttributeMaxDynamicSharedMemorySize,
                         SMEM_BYTES);
    cudaFuncSetAttribute(k_prep, cudaFuncAttributeMaxDynamicSharedMemorySize,
                         MOM_SMEM);

    k_prep<<<64, 256, MOM_SMEM>>>(feats, labels);
    k_moment2<<<KMOM + 1, 128>>>();
    k_main<<<NCTA_MAIN, 256, SMEM_BYTES>>>();
    k_final<<<32, 256>>>(labels, (float*)d_out);
}

// round 15
// speedup vs baseline: 1.3180x; 1.3180x over previous
#include <cuda_runtime.h>
#include <cuda_bf16.h>
#include <stdint.h>

// ============================================================================
// Problem constants
// ============================================================================
#define N_TOT 8192        // bsz * n_views
#define BSZ   4096
#define DIM   128
#define INV_T 14.285714285714286f   // 1 / 0.07
#define SPAD  136                    // padded SMEM row stride (elements)
#define NTILE 64
#define NPAIR 2080                   // 64*65/2 upper-triangular tiles
#define KMOM  12                     // Taylor terms for exp(li*lj)

typedef unsigned long long u64;

// ============================================================================
// Device globals
// ============================================================================
__device__ __nv_bfloat16 g_F[(size_t)N_TOT * DIM];     // normalized feats bf16
__device__ float g_Ff[(size_t)N_TOT * DIM];            // normalized feats fp32
__device__ float g_pD[(size_t)128 * N_TOT];            // D partials [slot][row]
__device__ float g_Gpart[128 * KMOM * DIM];            // moment partials (2/CTA)
__device__ float g_spart[64 * KMOM];
__device__ float g_G[KMOM * DIM];
__device__ float g_s[KMOM];
__device__ float g_A[N_TOT];
__device__ float g_W[N_TOT];
__device__ float g_bpart[32];
__device__ unsigned g_cnt;

__constant__ float c_CK[KMOM] = {
    1.0f, 1.0f, 0.5f, 1.6666667e-1f, 4.1666667e-2f, 8.3333333e-3f,
    1.3888889e-3f, 1.9841270e-4f, 2.4801587e-5f, 2.7557319e-6f,
    2.7557319e-7f, 2.5052108e-8f
};

__device__ __forceinline__ uint32_t smem_u32(const void* smem_ptr) {
    uint32_t addr;
    asm("{ .reg .u64 tmp; cvta.to.shared.u64 tmp, %1; cvt.u32.u64 %0, tmp; }"
        : "=r"(addr) : "l"(smem_ptr));
    return addr;
}

// ---- packed f32x2 helpers ----
__device__ __forceinline__ u64 pk2(float a, float b) {
    u64 r;
    asm("mov.b64 %0, {%1,%2};" : "=l"(r)
        : "r"(__float_as_uint(a)), "r"(__float_as_uint(b)));
    return r;
}
__device__ __forceinline__ void upk2(u64 v, float& a, float& b) {
    unsigned x, y;
    asm("mov.b64 {%0,%1}, %2;" : "=r"(x), "=r"(y) : "l"(v));
    a = __uint_as_float(x); b = __uint_as_float(y);
}
__device__ __forceinline__ u64 add2_(u64 a, u64 b) {
    u64 d; asm("add.rn.f32x2 %0,%1,%2;" : "=l"(d) : "l"(a), "l"(b)); return d;
}
__device__ __forceinline__ u64 fma2_(u64 a, u64 b, u64 c) {
    u64 d; asm("fma.rn.f32x2 %0,%1,%2,%3;" : "=l"(d) : "l"(a), "l"(b), "l"(c)); return d;
}
__device__ __forceinline__ float ex2f(float x) {
    float r; asm("ex2.approx.f32 %0,%1;" : "=f"(r) : "f"(x)); return r;
}

// ============================================================================
// Kernel 1 (fused prep): CTA c normalizes rows [c*128, c*128+128) into
//   g_F (bf16), g_Ff (fp32) and SMEM, then computes moment partials.
// ============================================================================
#define MOM_SMEM (128 * DIM * 4 + 128 * KMOM * 4)   // 64KB + 6KB

__global__ void __launch_bounds__(256)
k_prep(const float* __restrict__ feats, const float* __restrict__ labels) {
    extern __shared__ float smem_m[];
    float* sF     = smem_m;                 // [128 * DIM]
    float* s_coef = smem_m + 128 * DIM;     // [128][KMOM]
    int c   = blockIdx.x;
    int tid = threadIdx.x;
    int wid = tid >> 5;
    int lane = tid & 31;

#pragma unroll 4
    for (int i = 0; i < 16; ++i) {
        int j   = wid * 16 + i;
        int row = c * 128 + j;
        int b = row & (BSZ - 1);
        int v = row >> 12;
        float4 x = reinterpret_cast<const float4*>(feats)
                   [(size_t)(b * 2 + v) * (DIM / 4) + lane];
        float ss = fmaf(x.x, x.x, fmaf(x.y, x.y, fmaf(x.z, x.z, x.w * x.w)));
#pragma unroll
        for (int o = 16; o; o >>= 1) ss += __shfl_xor_sync(0xffffffffu, ss, o);
        float inv = rsqrtf(ss + 1e-12f);
        float4 xn;
        xn.x = x.x * inv; xn.y = x.y * inv; xn.z = x.z * inv; xn.w = x.w * inv;
        reinterpret_cast<float4*>(g_Ff)[(size_t)row * (DIM / 4) + lane] = xn;
        reinterpret_cast<float4*>(sF + j * DIM)[lane] = xn;
        __nv_bfloat162 lo = __floats2bfloat162_rn(xn.x, xn.y);
        __nv_bfloat162 hi = __floats2bfloat162_rn(xn.z, xn.w);
        uint2 pk;
        pk.x = *reinterpret_cast<uint32_t*>(&lo);
        pk.y = *reinterpret_cast<uint32_t*>(&hi);
        reinterpret_cast<uint2*>(g_F)[(size_t)row * (DIM / 4) + lane] = pk;
    }
    if (tid < 128) {
        int row = c * 128 + tid;
        float l = __ldg(&labels[row & (BSZ - 1)]);
        float b = expf(-0.5f * l * l);
        float p = b;
#pragma unroll
        for (int k = 0; k < KMOM; ++k) { s_coef[tid * KMOM + k] = p; p *= l; }
    }
    __syncthreads();

    int d = tid & 127;
    int h = tid >> 7;        // row half
    float acc[KMOM];
#pragma unroll
    for (int k = 0; k < KMOM; ++k) acc[k] = 0.f;
#pragma unroll 4
    for (int j = h * 64; j < h * 64 + 64; ++j) {
        float fv = sF[j * DIM + d];
#pragma unroll
        for (int k = 0; k < KMOM; ++k)
            acc[k] = fmaf(s_coef[j * KMOM + k], fv, acc[k]);
    }
#pragma unroll
    for (int k = 0; k < KMOM; ++k)
        g_Gpart[((c * 2 + h) * KMOM + k) * DIM + d] = acc[k];

    if (tid < KMOM) {
        float s = 0.f;
        for (int j = 0; j < 128; ++j) s += s_coef[j * KMOM + tid];
        g_spart[c * KMOM + tid] = s;
    }
}

// ============================================================================
// Kernel 2b: reduce 128 moment partials. Blocks 0..KMOM-1: G_k; block KMOM: s.
// ============================================================================
__global__ void __launch_bounds__(128)
k_moment2() {
    int k = blockIdx.x;
    int tid = threadIdx.x;
    if (k < KMOM) {
        float s = 0.f;
#pragma unroll 8
        for (int p = 0; p < 128; ++p)
            s += g_Gpart[(p * KMOM + k) * DIM + tid];
        g_G[k * DIM + tid] = s;
    } else if (tid < KMOM) {
        float s = 0.f;
        for (int c = 0; c < 64; ++c) s += g_spart[c * KMOM + tid];
        g_s[tid] = s;
    }
}

// ============================================================================
// Kernel 2c: per-row A_i, W_i. 512 CTAs, 2 rows/warp, G direct to registers,
//   no SMEM / no syncthreads, loads front-batched for MLP. (R8 measured 6.7us)
// ============================================================================
__global__ void __launch_bounds__(256)
k_rowAW(const float* __restrict__ labels) {
    int tid  = threadIdx.x;
    int wid  = tid >> 5;
    int lane = tid & 31;

    float4 gq[KMOM];
#pragma unroll
    for (int k = 0; k < KMOM; ++k)
        gq[k] = __ldg(&reinterpret_cast<const float4*>(g_G + k * DIM)[lane]);
    float sS[KMOM];
#pragma unroll
    for (int k = 0; k < KMOM; ++k) sS[k] = __ldg(&g_s[k]);

    int row0 = blockIdx.x * 16 + wid * 2;

    float l0 = __ldg(&labels[row0 & (BSZ - 1)]);
    float l1 = __ldg(&labels[(row0 + 1) & (BSZ - 1)]);
    float4 f0 = __ldg(&reinterpret_cast<const float4*>(g_Ff + (size_t)row0 * DIM)[lane]);
    float4 f1 = __ldg(&reinterpret_cast<const float4*>(g_Ff + (size_t)(row0 + 1) * DIM)[lane]);

    float val0 = 0.f, Wv0 = 0.f, p0 = 1.f;
    float val1 = 0.f, Wv1 = 0.f, p1 = 1.f;
#pragma unroll
    for (int k = 0; k < KMOM; ++k) {
        float tk0 = c_CK[k] * p0; p0 *= l0;
        float tk1 = c_CK[k] * p1; p1 *= l1;
        float dk0 = fmaf(f0.x, gq[k].x, fmaf(f0.y, gq[k].y,
                    fmaf(f0.z, gq[k].z, f0.w * gq[k].w)));
        float dk1 = fmaf(f1.x, gq[k].x, fmaf(f1.y, gq[k].y,
                    fmaf(f1.z, gq[k].z, f1.w * gq[k].w)));
        val0 = fmaf(tk0, dk0, val0);
        val1 = fmaf(tk1, dk1, val1);
        Wv0  = fmaf(tk0, sS[k], Wv0);
        Wv1  = fmaf(tk1, sS[k], Wv1);
    }
#pragma unroll
    for (int o = 16; o; o >>= 1) {
        val0 += __shfl_xor_sync(0xffffffffu, val0, o);
        val1 += __shfl_xor_sync(0xffffffffu, val1, o);
    }
    if (lane == 0) {
        float a0 = expf(-0.5f * l0 * l0);
        float a1 = expf(-0.5f * l1 * l1);
        g_A[row0]     = a0 * val0;
        g_W[row0]     = a0 * Wv0;
        g_A[row0 + 1] = a1 * val1;
        g_W[row0 + 1] = a1 * Wv1;
    }
}

// ============================================================================
// Kernel 3: fused 128x128 Gram tile, upper-triangular; D-epilogue only.
//   (Exact R9 version, measured 39.8 us: scalar B loads, scol overlay.)
// ============================================================================
#define SMEM_BYTES (2 * 128 * SPAD * 2)

__device__ __forceinline__ void ldmatrix_x4(uint32_t* a, uint32_t addr) {
    asm volatile("ldmatrix.sync.aligned.m8n8.x4.shared.b16 {%0,%1,%2,%3}, [%4];"
                 : "=r"(a[0]), "=r"(a[1]), "=r"(a[2]), "=r"(a[3]) : "r"(addr));
}
__device__ __forceinline__ void mma_bf16(float* c, const uint32_t* a,
                                         uint32_t b0, uint32_t b1) {
    asm volatile(
        "mma.sync.aligned.m16n8k16.row.col.f32.bf16.bf16.f32 "
        "{%0,%1,%2,%3}, {%4,%5,%6,%7}, {%8,%9}, {%0,%1,%2,%3};"
        : "+f"(c[0]), "+f"(c[1]), "+f"(c[2]), "+f"(c[3])
        : "r"(a[0]), "r"(a[1]), "r"(a[2]), "r"(a[3]), "r"(b0), "r"(b1));
}

__global__ void __launch_bounds__(256, 2)
k_main() {
    extern __shared__ char smem[];
    __nv_bfloat16* sA = reinterpret_cast<__nv_bfloat16*>(smem);
    __nv_bfloat16* sB = reinterpret_cast<__nv_bfloat16*>(smem + 128 * SPAD * 2);
    u64* scol = reinterpret_cast<u64*>(smem);   // overlay after MMA (16KB)

    int tid  = threadIdx.x;
    int wid  = tid >> 5;
    int lane = tid & 31;
    int rg = wid & 3;
    int cg = wid >> 2;

    int t = blockIdx.x;
    int tI;
    {
        float disc = (float)((2 * NTILE + 1) * (2 * NTILE + 1) - 8 * t);
        tI = (int)(((float)(2 * NTILE + 1) - sqrtf(disc)) * 0.5f);
        if (tI < 0) tI = 0;
        if (tI > NTILE - 1) tI = NTILE - 1;
        while (tI + 1 <= NTILE - 1 &&
               (tI + 1) * NTILE - ((tI + 1) * tI) / 2 <= t) ++tI;
        while (tI * NTILE - (tI * (tI - 1)) / 2 > t) --tI;
    }
    int tJ = tI + (t - (tI * NTILE - (tI * (tI - 1)) / 2));
    bool dtile = (tI == tJ);

    {
        const uint4* srcA = reinterpret_cast<const uint4*>(g_F + (size_t)tI * 128 * DIM);
        const uint4* srcB = reinterpret_cast<const uint4*>(g_F + (size_t)tJ * 128 * DIM);
#pragma unroll
        for (int it = 0; it < 8; ++it) {
            int c   = it * 256 + tid;
            int row = c >> 4;
            int ci  = c & 15;
            reinterpret_cast<uint4*>(sA + row * SPAD)[ci] = srcA[row * 16 + ci];
            reinterpret_cast<uint4*>(sB + row * SPAD)[ci] = srcB[row * 16 + ci];
        }
    }
    __syncthreads();

    float acc[2][8][4];
#pragma unroll
    for (int mt = 0; mt < 2; ++mt)
#pragma unroll
        for (int nt = 0; nt < 8; ++nt)
#pragma unroll
            for (int e = 0; e < 4; ++e) acc[mt][nt][e] = 0.f;

    uint32_t sA_b = smem_u32(sA);
    uint32_t sB_b = smem_u32(sB);
    uint32_t a_addr0 = sA_b + (uint32_t)(((rg * 32 + (lane & 15)) * SPAD
                                          + ((lane >> 4) << 3)) * 2);
    uint32_t b_addr0 = sB_b + (uint32_t)(((cg * 64 + (lane >> 2)) * SPAD
                                          + ((lane & 3) << 1)) * 2);

#pragma unroll
    for (int kc = 0; kc < 8; ++kc) {
        uint32_t a[2][4];
#pragma unroll
        for (int mt = 0; mt < 2; ++mt)
            ldmatrix_x4(a[mt], a_addr0 + (uint32_t)(mt * 16 * SPAD * 2 + kc * 32));
#pragma unroll
        for (int nt = 0; nt < 8; ++nt) {
            uint32_t baddr = b_addr0 + (uint32_t)(nt * 8 * SPAD * 2 + kc * 32);
            uint32_t b0, b1;
            asm volatile("ld.shared.b32 %0, [%1];" : "=r"(b0) : "r"(baddr));
            asm volatile("ld.shared.b32 %0, [%1];" : "=r"(b1) : "r"(baddr + 16));
            mma_bf16(acc[0][nt], a[0], b0, b1);
            mma_bf16(acc[1][nt], a[1], b0, b1);
        }
    }
    __syncthreads();   // tiles dead; scol writable

    const float C2s = 20.609929f;                  // INV_T * log2(e)
    const u64 C2p = pk2(C2s, C2s);
    const u64 C3p = pk2(-C2s, -C2s);

    int rl = rg * 32 + (lane >> 2);

    if (!dtile) {
        u64 sD2[4] = {0, 0, 0, 0};
#pragma unroll
        for (int nt = 0; nt < 8; ++nt) {
            u64 cD2 = 0;
#pragma unroll
            for (int mt = 0; mt < 2; ++mt) {
#pragma unroll
                for (int ee = 0; ee < 2; ++ee) {
                    int q = mt * 2 + ee;
                    u64 cos2 = pk2(acc[mt][nt][ee * 2], acc[mt][nt][ee * 2 + 1]);
                    u64 ea = fma2_(cos2, C2p, C3p);
                    float e0, e1; upk2(ea, e0, e1);
                    u64 ev = pk2(ex2f(e0), ex2f(e1));
                    sD2[q] = add2_(sD2[q], ev);
                    cD2 = add2_(cD2, ev);
                }
            }
            scol[(wid * 8 + nt) * 32 + lane] = cD2;
        }

#pragma unroll
        for (int q = 0; q < 4; ++q) {
            float d0, d1;
            upk2(sD2[q], d0, d1);
            float rD = d0 + d1;
            rD += __shfl_xor_sync(0xffffffffu, rD, 1);
            rD += __shfl_xor_sync(0xffffffffu, rD, 2);
            if ((lane & 3) == 0) {
                int slot = tJ * 2 + cg;
                int gi = tI * 128 + rl + q * 8;
                g_pD[(size_t)slot * N_TOT + gi] = rD;
            }
        }

        __syncthreads();
        if (tid < 64) {
            int cgx = tid >> 5;
            int ntx = (tid >> 2) & 7;
            int pl  = tid & 3;
            u64 vD = 0;
#pragma unroll
            for (int rgx = 0; rgx < 4; ++rgx) {
                int widx = cgx * 4 + rgx;
#pragma unroll
                for (int lg = 0; lg < 8; ++lg)
                    vD = add2_(vD, scol[(widx * 8 + ntx) * 32 + lg * 4 + pl]);
            }
            float d0, d1; upk2(vD, d0, d1);
            int gc = tJ * 128 + tid * 2;
            int slot = tI * 2 + cgx;
            float2 fd = {d0, d1};
            *reinterpret_cast<float2*>(&g_pD[(size_t)slot * N_TOT + gc]) = fd;
        }
    } else {
        float sDr[4] = {0.f, 0.f, 0.f, 0.f};
#pragma unroll
        for (int nt = 0; nt < 8; ++nt) {
            int clbase = cg * 64 + nt * 8 + ((lane & 3) << 1);
#pragma unroll
            for (int mt = 0; mt < 2; ++mt) {
#pragma unroll
                for (int e = 0; e < 4; ++e) {
                    int q  = mt * 2 + (e >> 1);
                    int rr = rl + q * 8;
                    int cc = clbase + (e & 1);
                    float ev = (rr == cc) ? 0.f
                             : ex2f(fmaf(acc[mt][nt][e], C2s, -C2s));
                    sDr[q] += ev;
                }
            }
        }
#pragma unroll
        for (int q = 0; q < 4; ++q) {
            sDr[q] += __shfl_xor_sync(0xffffffffu, sDr[q], 1);
            sDr[q] += __shfl_xor_sync(0xffffffffu, sDr[q], 2);
        }
        if ((lane & 3) == 0) {
            int slot = tJ * 2 + cg;
#pragma unroll
            for (int q = 0; q < 4; ++q) {
                int gi = tI * 128 + rl + q * 8;
                g_pD[(size_t)slot * N_TOT + gi] = sDr[q];
            }
        }
    }
}

// ============================================================================
// Kernel 4: per-row D reduction + loss + fused global mean (R8 version).
// ============================================================================
__global__ void k_final1(float* __restrict__ out) {
    __shared__ float red[32];
    __shared__ bool s_last;
    int tid = threadIdx.x;
    int row = blockIdx.x * 256 + tid;   // 32 CTAs x 256 = 8192
    float D = 0.f;
#pragma unroll 8
    for (int s = 0; s < 128; ++s)
        D += g_pD[(size_t)s * N_TOT + row];
    float A = g_A[row];
    float W = g_W[row];
    float loss = -((A - W) * INV_T / W - logf(D + 1e-8f));
#pragma unroll
    for (int o = 16; o; o >>= 1) loss += __shfl_xor_sync(0xffffffffu, loss, o);
    if ((tid & 31) == 0) red[tid >> 5] = loss;
    __syncthreads();
    if (tid < 8) {
        float v = red[tid];
#pragma unroll
        for (int o = 4; o; o >>= 1) v += __shfl_xor_sync(0xffu, v, o);
        if (tid == 0) g_bpart[blockIdx.x] = v;
    }
    __threadfence();
    if (tid == 0) s_last = (atomicAdd(&g_cnt, 1u) == 31u);
    __syncthreads();
    if (s_last && tid < 32) {
        float v;
        asm volatile("ld.global.cg.f32 %0, [%1];" : "=f"(v) : "l"(&g_bpart[tid]));
#pragma unroll
        for (int o = 16; o; o >>= 1) v += __shfl_xor_sync(0xffffffffu, v, o);
        if (tid == 0) {
            out[0] = v * (1.0f / (float)N_TOT);
            g_cnt = 0u;   // reset for next graph replay
        }
    }
}

// ============================================================================
// Launch: fork the moment chain onto a side stream so it overlaps k_main.
//   Dependencies: prep -> {moment2 -> rowAW} || {main} -> final1.
//   Event fork/join is the standard graph-capture pattern (event nodes).
// ============================================================================
extern "C" void kernel_launch(void* const* d_in, const int* in_sizes, int n_in,
                              void* d_out, int out_size) {
    const float* feats  = (const float*)d_in[0];
    const float* labels = (const float*)d_in[1];
    if (n_in >= 2 && in_sizes[0] == BSZ && in_sizes[1] != BSZ) {
        feats  = (const float*)d_in[1];
        labels = (const float*)d_in[0];
    }

    static cudaStream_t s_side = nullptr;
    static cudaEvent_t ev_fork = nullptr, ev_join = nullptr;
    if (s_side == nullptr) {
        cudaStreamCreateWithFlags(&s_side, cudaStreamNonBlocking);
        cudaEventCreateWithFlags(&ev_fork, cudaEventDisableTiming);
        cudaEventCreateWithFlags(&ev_join, cudaEventDisableTiming);
    }

    cudaFuncSetAttribute(k_main, cudaFuncAttributeMaxDynamicSharedMemorySize,
                         SMEM_BYTES);
    cudaFuncSetAttribute(k_prep, cudaFuncAttributeMaxDynamicSharedMemorySize,
                         MOM_SMEM);

    k_prep<<<64, 256, MOM_SMEM>>>(feats, labels);

    cudaEventRecord(ev_fork, 0);
    cudaStreamWaitEvent(s_side, ev_fork, 0);
    k_moment2<<<KMOM + 1, 128, 0, s_side>>>();
    k_rowAW<<<512, 256, 0, s_side>>>(labels);
    cudaEventRecord(ev_join, s_side);

    k_main<<<NPAIR, 256, SMEM_BYTES>>>();     // overlaps the side stream

    cudaStreamWaitEvent(0, ev_join, 0);
    k_final1<<<32, 256>>>((float*)d_out);
}